// round 1
// baseline (speedup 1.0000x reference)
#include <cuda_runtime.h>
#include <math.h>

// Problem constants
#define BMAX   16384
#define INDIM  128      // STATE + N_U
#define STATE  64
#define HID    1024
#define NB     8        // GRID + K
#define KACT   (INDIM + INDIM * NB)   // 1152 = silu cols + basis cols
#define NOUT2  (8192 + 64)            // 8256 = STATE*INDIM + STATE

// ---------------- scratch (device globals; no allocations allowed) ----------
__device__ float g_x   [BMAX * INDIM];     //  8 MB : concat(state, novelU)
__device__ float g_act [BMAX * KACT];      // 75 MB : [silu(x) | bases]
__device__ float g_kan [BMAX * HID];       // 67 MB
__device__ float g_W1  [KACT * HID];       //  4.7 MB: [scale_base ; scale_sp*coef]
__device__ float g_W2  [HID * NOUT2];      // 33.8 MB: [f_w | bias_w]
__device__ float g_b2  [NOUT2];            //         [f_b | bias_b]

// ---------------- weight prep ----------------
__global__ void prep_W1(const float* __restrict__ scale_base,
                        const float* __restrict__ scale_sp,
                        const float* __restrict__ coef) {
    int idx = blockIdx.x * blockDim.x + threadIdx.x;
    if (idx >= KACT * HID) return;
    int k = idx / HID, o = idx - k * HID;
    float v;
    if (k < INDIM) {
        v = scale_base[k * HID + o];
    } else {
        int kk = k - INDIM;
        int i = kk >> 3, c = kk & 7;
        v = scale_sp[i * HID + o] * coef[(i * HID + o) * NB + c];
    }
    g_W1[idx] = v;
}

__global__ void prep_W2(const float* __restrict__ f_w,
                        const float* __restrict__ bias_w,
                        const float* __restrict__ f_b,
                        const float* __restrict__ bias_b) {
    int idx = blockIdx.x * blockDim.x + threadIdx.x;
    if (idx < NOUT2)
        g_b2[idx] = (idx < 8192) ? f_b[idx] : bias_b[idx - 8192];
    if (idx >= HID * NOUT2) return;
    int h = idx / NOUT2, n = idx - h * NOUT2;
    g_W2[idx] = (n < 8192) ? f_w[h * 8192 + n] : bias_w[h * 64 + (n - 8192)];
}

// ---------------- activation build: silu + Cox-de-Boor B-splines ------------
// knot t_j = -1 + 0.4*(j-3), j = 0..11  (GRID+2K+1 = 12 knots), matching the
// float32 arithmetic of the reference (h = 2/5 exactly representable? 0.4f).
__device__ __forceinline__ float knot(int j) {
    return -1.0f + 0.4f * (float)(j - 3);
}

__global__ void build_act(const float* __restrict__ state,
                          const float* __restrict__ novelU, int B) {
    int idx = blockIdx.x * blockDim.x + threadIdx.x;
    if (idx >= B * INDIM) return;
    int b = idx / INDIM, i = idx - b * INDIM;
    float x = (i < STATE) ? state[b * STATE + i] : novelU[b * (INDIM - STATE) + (i - STATE)];
    g_x[b * INDIM + i] = x;
    // silu
    g_act[b * KACT + i] = x / (1.0f + expf(-x));
    // order-0 bases (11), then 3 Cox-de-Boor elevations -> 8 bases
    float bb[11];
#pragma unroll
    for (int j = 0; j < 11; j++)
        bb[j] = (x >= knot(j) && x < knot(j + 1)) ? 1.0f : 0.0f;
#pragma unroll
    for (int ord = 1; ord <= 3; ord++) {
#pragma unroll
        for (int j = 0; j < 11 - 1; j++) {
            if (j >= 11 - ord) break;
            float l = (x - knot(j)) / (knot(j + ord) - knot(j));
            float r = (knot(j + ord + 1) - x) / (knot(j + ord + 1) - knot(j + 1));
            bb[j] = l * bb[j] + r * bb[j + 1];
        }
    }
    float* dst = &g_act[b * KACT + INDIM + i * NB];
#pragma unroll
    for (int c = 0; c < NB; c++) dst[c] = bb[c];
}

// ---------------- SGEMM: 128x128 block, 8x8 per thread, BK=8 ----------------
// GEMM1: g_kan[B,1024] = g_act[B,1152] @ g_W1[1152,1024]
__global__ __launch_bounds__(256) void sgemm1(int B) {
    const int K = KACT, N = HID;
    __shared__ float As[8][128];
    __shared__ float Bs[8][128];
    int tid = threadIdx.x;
    int row0 = blockIdx.y * 128, col0 = blockIdx.x * 128;
    int ar = tid >> 1, ac = (tid & 1) * 4;
    int br = tid >> 5, bc = (tid & 31) * 4;
    int ty = tid >> 4, tx = tid & 15;
    const float* Ap = g_act + (size_t)(row0 + ar) * K + ac;
    const float* Bp = g_W1 + (size_t)br * N + col0 + bc;
    float acc[8][8];
#pragma unroll
    for (int m = 0; m < 8; m++)
#pragma unroll
        for (int n = 0; n < 8; n++) acc[m][n] = 0.0f;

    for (int k0 = 0; k0 < K; k0 += 8) {
        float4 av = *(const float4*)(Ap + k0);
        As[ac + 0][ar] = av.x; As[ac + 1][ar] = av.y;
        As[ac + 2][ar] = av.z; As[ac + 3][ar] = av.w;
        float4 bv = *(const float4*)(Bp + (size_t)k0 * N);
        *(float4*)&Bs[br][bc] = bv;
        __syncthreads();
#pragma unroll
        for (int kk = 0; kk < 8; kk++) {
            float a[8], bvv[8];
            *(float4*)&a[0]   = *(const float4*)&As[kk][ty * 8];
            *(float4*)&a[4]   = *(const float4*)&As[kk][ty * 8 + 4];
            *(float4*)&bvv[0] = *(const float4*)&Bs[kk][tx * 8];
            *(float4*)&bvv[4] = *(const float4*)&Bs[kk][tx * 8 + 4];
#pragma unroll
            for (int m = 0; m < 8; m++)
#pragma unroll
                for (int n = 0; n < 8; n++) acc[m][n] = fmaf(a[m], bvv[n], acc[m][n]);
        }
        __syncthreads();
    }
#pragma unroll
    for (int m = 0; m < 8; m++) {
        float* dst = &g_kan[(size_t)(row0 + ty * 8 + m) * HID + col0 + tx * 8];
        *(float4*)dst       = *(float4*)&acc[m][0];
        *(float4*)(dst + 4) = *(float4*)&acc[m][4];
    }
}

// GEMM2: [AB | bias] = g_kan[B,1024] @ g_W2[1024,8256] + g_b2
__global__ __launch_bounds__(256) void sgemm2(float* __restrict__ outAB,
                                              float* __restrict__ outBias, int B) {
    const int K = HID, N = NOUT2;
    __shared__ float As[8][128];
    __shared__ float Bs[8][128];
    int tid = threadIdx.x;
    int row0 = blockIdx.y * 128, col0 = blockIdx.x * 128;
    int ar = tid >> 1, ac = (tid & 1) * 4;
    int br = tid >> 5, bc = (tid & 31) * 4;
    int ty = tid >> 4, tx = tid & 15;
    const float* Ap = g_kan + (size_t)(row0 + ar) * K + ac;
    const float* Bp = g_W2 + (size_t)br * N + col0 + bc;
    bool bvalid = (col0 + bc) < N;   // N % 4 == 0, bc multiple of 4 => whole-vec valid/invalid
    float acc[8][8];
#pragma unroll
    for (int m = 0; m < 8; m++)
#pragma unroll
        for (int n = 0; n < 8; n++) acc[m][n] = 0.0f;

    for (int k0 = 0; k0 < K; k0 += 8) {
        float4 av = *(const float4*)(Ap + k0);
        As[ac + 0][ar] = av.x; As[ac + 1][ar] = av.y;
        As[ac + 2][ar] = av.z; As[ac + 3][ar] = av.w;
        float4 bv = make_float4(0.f, 0.f, 0.f, 0.f);
        if (bvalid) bv = *(const float4*)(Bp + (size_t)k0 * N);
        *(float4*)&Bs[br][bc] = bv;
        __syncthreads();
#pragma unroll
        for (int kk = 0; kk < 8; kk++) {
            float a[8], bvv[8];
            *(float4*)&a[0]   = *(const float4*)&As[kk][ty * 8];
            *(float4*)&a[4]   = *(const float4*)&As[kk][ty * 8 + 4];
            *(float4*)&bvv[0] = *(const float4*)&Bs[kk][tx * 8];
            *(float4*)&bvv[4] = *(const float4*)&Bs[kk][tx * 8 + 4];
#pragma unroll
            for (int m = 0; m < 8; m++)
#pragma unroll
                for (int n = 0; n < 8; n++) acc[m][n] = fmaf(a[m], bvv[n], acc[m][n]);
        }
        __syncthreads();
    }
#pragma unroll
    for (int m = 0; m < 8; m++) {
        int row = row0 + ty * 8 + m;
#pragma unroll
        for (int nn = 0; nn < 8; nn++) {
            int n = col0 + tx * 8 + nn;
            if (n >= N) continue;
            float v = acc[m][nn] + g_b2[n];
            if (n < 8192) outAB[(size_t)row * 8192 + n] = v;
            else          outBias[(size_t)row * 64 + (n - 8192)] = v;
        }
    }
}

// ---------------- final: out[b,s] = AB[b,s,:] . x[b] + bias[b,s] ------------
__global__ void final_k(const float* __restrict__ AB,
                        const float* __restrict__ biasOut,
                        float* __restrict__ outO) {
    int b = blockIdx.x;
    int s = threadIdx.x;   // 64 threads
    __shared__ float xs[INDIM];
    xs[s]      = g_x[b * INDIM + s];
    xs[s + 64] = g_x[b * INDIM + 64 + s];
    __syncthreads();
    const float* row = AB + (size_t)b * 8192 + (size_t)s * 128;
    float acc = biasOut[(size_t)b * 64 + s];
#pragma unroll
    for (int u = 0; u < 128; u += 4) {
        float4 v = *(const float4*)(row + u);
        acc = fmaf(v.x, xs[u], acc);
        acc = fmaf(v.y, xs[u + 1], acc);
        acc = fmaf(v.z, xs[u + 2], acc);
        acc = fmaf(v.w, xs[u + 3], acc);
    }
    outO[(size_t)b * 64 + s] = acc;
}

// ---------------- launch ----------------
extern "C" void kernel_launch(void* const* d_in, const int* in_sizes, int n_in,
                              void* d_out, int out_size) {
    const float* novelU     = (const float*)d_in[0];
    const float* state      = (const float*)d_in[1];
    const float* coef       = (const float*)d_in[2];
    const float* scale_base = (const float*)d_in[3];
    const float* scale_sp   = (const float*)d_in[4];
    const float* bias_w     = (const float*)d_in[5];
    const float* bias_b     = (const float*)d_in[6];
    const float* f_w        = (const float*)d_in[7];
    const float* f_b        = (const float*)d_in[8];
    float* out = (float*)d_out;

    int B = in_sizes[0] / 64;
    if (B > BMAX) B = BMAX;

    float* outO    = out;                                   // [B,64]
    float* outAB   = out + (size_t)B * 64;                  // [B,64,128]
    float* outBias = out + (size_t)B * 64 + (size_t)B * 8192; // [B,64]

    prep_W1 <<<(KACT * HID + 255) / 256, 256>>>(scale_base, scale_sp, coef);
    prep_W2 <<<(HID * NOUT2 + 255) / 256, 256>>>(f_w, bias_w, f_b, bias_b);
    build_act<<<(B * INDIM + 255) / 256, 256>>>(state, novelU, B);

    dim3 g1(HID / 128, B / 128);
    sgemm1<<<g1, 256>>>(B);

    dim3 g2((NOUT2 + 127) / 128, B / 128);
    sgemm2<<<g2, 256>>>(outAB, outBias, B);

    final_k<<<B, 64>>>(outAB, outBias, outO);
}

// round 2
// speedup vs baseline: 3.6142x; 3.6142x over previous
#include <cuda_runtime.h>
#include <math.h>
#include <stdint.h>

// Problem constants
#define BMAX   16384
#define INDIM  128
#define STATE  64
#define HID    1024
#define NB     8
#define KACT   (INDIM + INDIM * NB)   // 1152
#define NOUT2  (8192 + 64)            // 8256
#define NOUT2P 8320                   // padded to multiple of 128

// ---------------- scratch ----------------
__device__ float g_x   [BMAX * INDIM];
__device__ float g_act [BMAX * KACT];
__device__ float g_kan [BMAX * HID];
__device__ float g_W1T [HID * KACT];       // [o][k], tf32-rounded
__device__ float g_W2T [NOUT2P * HID];     // [n][h], tf32-rounded, zero-padded rows
__device__ float g_b2  [NOUT2];

// ---------------- tf32 helpers ----------------
__device__ __forceinline__ uint32_t f2tf(float f) {
    uint32_t r;
    asm("cvt.rna.tf32.f32 %0, %1;" : "=r"(r) : "f"(f));
    return r;
}

__device__ __forceinline__ void ldsm4(uint32_t addr, uint32_t& r0, uint32_t& r1,
                                      uint32_t& r2, uint32_t& r3) {
    asm volatile("ldmatrix.sync.aligned.m8n8.x4.shared.b16 {%0,%1,%2,%3}, [%4];"
                 : "=r"(r0), "=r"(r1), "=r"(r2), "=r"(r3) : "r"(addr));
}

__device__ __forceinline__ void mma_tf32(float* d, const uint32_t* a, const uint32_t* b) {
    asm volatile(
        "mma.sync.aligned.m16n8k8.row.col.f32.tf32.tf32.f32 "
        "{%0,%1,%2,%3}, {%4,%5,%6,%7}, {%8,%9}, {%0,%1,%2,%3};"
        : "+f"(d[0]), "+f"(d[1]), "+f"(d[2]), "+f"(d[3])
        : "r"(a[0]), "r"(a[1]), "r"(a[2]), "r"(a[3]), "r"(b[0]), "r"(b[1]));
}

// ---------------- weight prep ----------------
__global__ void prep_W1T(const float* __restrict__ scale_base,
                         const float* __restrict__ scale_sp,
                         const float* __restrict__ coef) {
    int idx = blockIdx.x * blockDim.x + threadIdx.x;
    if (idx >= HID * KACT) return;
    int o = idx / KACT, k = idx - o * KACT;
    float v;
    if (k < INDIM) {
        v = scale_base[k * HID + o];
    } else {
        int kk = k - INDIM;
        int i = kk >> 3, c = kk & 7;
        v = scale_sp[i * HID + o] * coef[(i * HID + o) * NB + c];
    }
    ((uint32_t*)g_W1T)[idx] = f2tf(v);
}

__global__ void prep_b2(const float* __restrict__ f_b, const float* __restrict__ bias_b) {
    int idx = blockIdx.x * blockDim.x + threadIdx.x;
    if (idx >= NOUT2) return;
    g_b2[idx] = (idx < 8192) ? f_b[idx] : bias_b[idx - 8192];
}

// transpose [HID][NOUT2-ish] -> W2T[NOUT2P][HID], tf32-rounded, zero pad
__global__ void prep_W2T(const float* __restrict__ f_w, const float* __restrict__ bias_w) {
    __shared__ float tile[32][33];
    int n0 = blockIdx.x * 32, h0 = blockIdx.y * 32;
    int tx = threadIdx.x, ty = threadIdx.y;
    int n = n0 + tx, h = h0 + ty;
    float v = 0.0f;
    if (n < 8192)       v = f_w[(size_t)h * 8192 + n];
    else if (n < NOUT2) v = bias_w[h * 64 + (n - 8192)];
    tile[ty][tx] = v;
    __syncthreads();
    // write W2T[n0+ty][h0+tx]
    ((uint32_t*)g_W2T)[(size_t)(n0 + ty) * HID + h0 + tx] = f2tf(tile[tx][ty]);
}

// ---------------- activation build ----------------
__device__ __forceinline__ float knot(int j) { return -1.0f + 0.4f * (float)(j - 3); }

__global__ void build_act(const float* __restrict__ state,
                          const float* __restrict__ novelU, int B) {
    int idx = blockIdx.x * blockDim.x + threadIdx.x;
    if (idx >= B * INDIM) return;
    int b = idx / INDIM, i = idx - b * INDIM;
    float x = (i < STATE) ? state[b * STATE + i] : novelU[b * (INDIM - STATE) + (i - STATE)];
    g_x[b * INDIM + i] = x;
    g_act[(size_t)b * KACT + i] = x / (1.0f + expf(-x));
    float bb[11];
#pragma unroll
    for (int j = 0; j < 11; j++)
        bb[j] = (x >= knot(j) && x < knot(j + 1)) ? 1.0f : 0.0f;
#pragma unroll
    for (int ord = 1; ord <= 3; ord++) {
#pragma unroll
        for (int j = 0; j < 11 - 1; j++) {
            if (j >= 11 - ord) break;
            float l = (x - knot(j)) / (knot(j + ord) - knot(j));
            float r = (knot(j + ord + 1) - x) / (knot(j + ord + 1) - knot(j + 1));
            bb[j] = l * bb[j] + r * bb[j + 1];
        }
    }
    float* dst = &g_act[(size_t)b * KACT + INDIM + i * NB];
    float4 v0 = make_float4(bb[0], bb[1], bb[2], bb[3]);
    float4 v1 = make_float4(bb[4], bb[5], bb[6], bb[7]);
    *(float4*)dst = v0;
    *(float4*)(dst + 4) = v1;
}

// ---------------- TF32 tensor-core GEMM ----------------
// C[M,*] = A[M,K] @ Bt[N,K]^T, 128x128 CTA tile, BK=32, 8 warps of 64x32.
// EPI2: add g_b2, split into outAB (n<8192) / outBias.
#define SA 36   // smem row stride (u32), 144B = 9*16B -> conflict-free ldmatrix

template<int K, bool EPI2>
__global__ __launch_bounds__(256) void mma_gemm(const float* __restrict__ A,
                                                const float* __restrict__ Bt,
                                                float* __restrict__ C,
                                                float* __restrict__ outAB,
                                                float* __restrict__ outBias) {
    __shared__ uint32_t As[128 * SA];
    __shared__ uint32_t Bs[128 * SA];

    int tid = threadIdx.x;
    int lane = tid & 31, wid = tid >> 5;
    int row0 = blockIdx.y * 128, col0 = blockIdx.x * 128;
    int m0w = (wid & 1) * 64;
    int n0w = (wid >> 1) * 32;

    // ldmatrix lane address components
    int rowA = (lane & 7) + 8 * ((lane >> 3) & 1);
    int kA   = 4 * (lane >> 4);
    int rowB = (lane & 7) + 8 * (lane >> 4);
    int kB   = 4 * ((lane >> 3) & 1);

    uint32_t sA = (uint32_t)__cvta_generic_to_shared(As);
    uint32_t sB = (uint32_t)__cvta_generic_to_shared(Bs);

    float acc[4][4][4];
#pragma unroll
    for (int mt = 0; mt < 4; mt++)
#pragma unroll
        for (int nt = 0; nt < 4; nt++)
#pragma unroll
            for (int j = 0; j < 4; j++) acc[mt][nt][j] = 0.0f;

    int cr = tid >> 3;            // copy row 0..31 step -> 128 rows over 4 iters
    int cc = (tid & 7) * 4;       // copy col

    for (int k0 = 0; k0 < K; k0 += 32) {
        __syncthreads();
#pragma unroll
        for (int i = 0; i < 4; i++) {
            int r = cr + i * 32;
            float4 av = *(const float4*)(A + (size_t)(row0 + r) * K + k0 + cc);
            uint32_t* da = &As[r * SA + cc];
            da[0] = f2tf(av.x); da[1] = f2tf(av.y); da[2] = f2tf(av.z); da[3] = f2tf(av.w);
            float4 bv = *(const float4*)(Bt + (size_t)(col0 + r) * K + k0 + cc);
            uint32_t* db = &Bs[r * SA + cc];
            da = db;
            da[0] = __float_as_uint(bv.x); da[1] = __float_as_uint(bv.y);
            da[2] = __float_as_uint(bv.z); da[3] = __float_as_uint(bv.w);
        }
        __syncthreads();

#pragma unroll
        for (int kk = 0; kk < 32; kk += 8) {
            uint32_t a[4][4], b[4][2];
#pragma unroll
            for (int mt = 0; mt < 4; mt++) {
                uint32_t addr = sA + ((m0w + mt * 16 + rowA) * SA + kk + kA) * 4;
                ldsm4(addr, a[mt][0], a[mt][1], a[mt][2], a[mt][3]);
            }
#pragma unroll
            for (int np = 0; np < 2; np++) {
                uint32_t addr = sB + ((n0w + np * 16 + rowB) * SA + kk + kB) * 4;
                ldsm4(addr, b[2 * np][0], b[2 * np][1], b[2 * np + 1][0], b[2 * np + 1][1]);
            }
#pragma unroll
            for (int mt = 0; mt < 4; mt++)
#pragma unroll
                for (int nt = 0; nt < 4; nt++)
                    mma_tf32(acc[mt][nt], a[mt], b[nt]);
        }
    }

    // epilogue
    int gid = lane >> 2, tig = lane & 3;
#pragma unroll
    for (int mt = 0; mt < 4; mt++) {
#pragma unroll
        for (int nt = 0; nt < 4; nt++) {
            int r0r = row0 + m0w + mt * 16 + gid;
            int n   = col0 + n0w + nt * 8 + 2 * tig;
            if (!EPI2) {
                float2 v01 = make_float2(acc[mt][nt][0], acc[mt][nt][1]);
                float2 v23 = make_float2(acc[mt][nt][2], acc[mt][nt][3]);
                *(float2*)(C + (size_t)r0r * HID + n)       = v01;
                *(float2*)(C + (size_t)(r0r + 8) * HID + n) = v23;
            } else {
                if (n >= NOUT2) continue;
                float b0 = g_b2[n], b1 = g_b2[n + 1];
                float2 v01 = make_float2(acc[mt][nt][0] + b0, acc[mt][nt][1] + b1);
                float2 v23 = make_float2(acc[mt][nt][2] + b0, acc[mt][nt][3] + b1);
                if (n < 8192) {
                    *(float2*)(outAB + (size_t)r0r * 8192 + n)       = v01;
                    *(float2*)(outAB + (size_t)(r0r + 8) * 8192 + n) = v23;
                } else {
                    int nb = n - 8192;
                    *(float2*)(outBias + (size_t)r0r * 64 + nb)       = v01;
                    *(float2*)(outBias + (size_t)(r0r + 8) * 64 + nb) = v23;
                }
            }
        }
    }
}

// ---------------- final: out[b,s] = AB[b,s,:] . x[b] + bias[b,s] ------------
__global__ void final_k(const float* __restrict__ AB,
                        const float* __restrict__ biasOut,
                        float* __restrict__ outO) {
    int b = blockIdx.x;
    int s = threadIdx.x;
    __shared__ float xs[INDIM];
    xs[s]      = g_x[b * INDIM + s];
    xs[s + 64] = g_x[b * INDIM + 64 + s];
    __syncthreads();
    const float* row = AB + (size_t)b * 8192 + (size_t)s * 128;
    float acc = biasOut[(size_t)b * 64 + s];
#pragma unroll
    for (int u = 0; u < 128; u += 4) {
        float4 v = *(const float4*)(row + u);
        acc = fmaf(v.x, xs[u], acc);
        acc = fmaf(v.y, xs[u + 1], acc);
        acc = fmaf(v.z, xs[u + 2], acc);
        acc = fmaf(v.w, xs[u + 3], acc);
    }
    outO[(size_t)b * 64 + s] = acc;
}

// ---------------- launch ----------------
extern "C" void kernel_launch(void* const* d_in, const int* in_sizes, int n_in,
                              void* d_out, int out_size) {
    const float* novelU     = (const float*)d_in[0];
    const float* state      = (const float*)d_in[1];
    const float* coef       = (const float*)d_in[2];
    const float* scale_base = (const float*)d_in[3];
    const float* scale_sp   = (const float*)d_in[4];
    const float* bias_w     = (const float*)d_in[5];
    const float* bias_b     = (const float*)d_in[6];
    const float* f_w        = (const float*)d_in[7];
    const float* f_b        = (const float*)d_in[8];
    float* out = (float*)d_out;

    int B = in_sizes[0] / 64;
    if (B > BMAX) B = BMAX;

    float* outO    = out;
    float* outAB   = out + (size_t)B * 64;
    float* outBias = out + (size_t)B * 64 + (size_t)B * 8192;

    prep_W1T<<<(HID * KACT + 255) / 256, 256>>>(scale_base, scale_sp, coef);
    prep_W2T<<<dim3(NOUT2P / 32, HID / 32), dim3(32, 32)>>>(f_w, bias_w);
    prep_b2<<<(NOUT2 + 255) / 256, 256>>>(f_b, bias_b);
    build_act<<<(B * INDIM + 255) / 256, 256>>>(state, novelU, B);

    float* d_kan;
    cudaGetSymbolAddress((void**)&d_kan, g_kan);
    float* d_act;
    cudaGetSymbolAddress((void**)&d_act, g_act);
    float* d_W1T;
    cudaGetSymbolAddress((void**)&d_W1T, g_W1T);
    float* d_W2T;
    cudaGetSymbolAddress((void**)&d_W2T, g_W2T);

    dim3 g1(HID / 128, B / 128);
    mma_gemm<KACT, false><<<g1, 256>>>(d_act, d_W1T, d_kan, nullptr, nullptr);

    dim3 g2(NOUT2P / 128, B / 128);
    mma_gemm<HID, true><<<g2, 256>>>(d_kan, d_W2T, nullptr, outAB, outBias);

    final_k<<<B, 64>>>(outAB, outBias, outO);
}

// round 3
// speedup vs baseline: 3.8381x; 1.0620x over previous
#include <cuda_runtime.h>
#include <math.h>
#include <stdint.h>

// Problem constants
#define BMAX   16384
#define INDIM  128
#define STATE  64
#define HID    1024
#define NB     8
#define KACT   (INDIM + INDIM * NB)   // 1152
#define NOUT2  (8192 + 64)            // 8256
#define NOUT2P 8320                   // padded to multiple of 128

// ---------------- scratch ----------------
__device__ float g_x   [BMAX * INDIM];
__device__ float g_act [BMAX * KACT];      // tf32-rounded values
__device__ float g_kan [BMAX * HID];       // tf32-rounded values
__device__ float g_W1T [HID * KACT];       // [o][k], tf32-rounded
__device__ float g_W2T [NOUT2P * HID];     // [n][h], tf32-rounded, zero-padded rows
__device__ float g_b2  [NOUT2];

// ---------------- helpers ----------------
__device__ __forceinline__ uint32_t f2tf(float f) {
    uint32_t r;
    asm("cvt.rna.tf32.f32 %0, %1;" : "=r"(r) : "f"(f));
    return r;
}
__device__ __forceinline__ float f2tf_f(float f) { return __uint_as_float(f2tf(f)); }

__device__ __forceinline__ void ldsm4(uint32_t addr, uint32_t& r0, uint32_t& r1,
                                      uint32_t& r2, uint32_t& r3) {
    asm volatile("ldmatrix.sync.aligned.m8n8.x4.shared.b16 {%0,%1,%2,%3}, [%4];"
                 : "=r"(r0), "=r"(r1), "=r"(r2), "=r"(r3) : "r"(addr));
}

__device__ __forceinline__ void mma_tf32(float* d, const uint32_t* a, const uint32_t* b) {
    asm volatile(
        "mma.sync.aligned.m16n8k8.row.col.f32.tf32.tf32.f32 "
        "{%0,%1,%2,%3}, {%4,%5,%6,%7}, {%8,%9}, {%0,%1,%2,%3};"
        : "+f"(d[0]), "+f"(d[1]), "+f"(d[2]), "+f"(d[3])
        : "r"(a[0]), "r"(a[1]), "r"(a[2]), "r"(a[3]), "r"(b[0]), "r"(b[1]));
}

__device__ __forceinline__ void cpa16(uint32_t smem, const void* g) {
    asm volatile("cp.async.cg.shared.global [%0], [%1], 16;" :: "r"(smem), "l"(g));
}
__device__ __forceinline__ void cpa_commit() { asm volatile("cp.async.commit_group;"); }
__device__ __forceinline__ void cpa_wait1()  { asm volatile("cp.async.wait_group 1;"); }
__device__ __forceinline__ void cpa_wait0()  { asm volatile("cp.async.wait_group 0;"); }

// ---------------- weight prep ----------------
__global__ void prep_W1T(const float* __restrict__ scale_base,
                         const float* __restrict__ scale_sp,
                         const float* __restrict__ coef) {
    int idx = blockIdx.x * blockDim.x + threadIdx.x;
    if (idx >= HID * KACT) return;
    int o = idx / KACT, k = idx - o * KACT;
    float v;
    if (k < INDIM) {
        v = scale_base[k * HID + o];
    } else {
        int kk = k - INDIM;
        int i = kk >> 3, c = kk & 7;
        v = scale_sp[i * HID + o] * coef[(i * HID + o) * NB + c];
    }
    ((uint32_t*)g_W1T)[idx] = f2tf(v);
}

__global__ void prep_b2(const float* __restrict__ f_b, const float* __restrict__ bias_b) {
    int idx = blockIdx.x * blockDim.x + threadIdx.x;
    if (idx >= NOUT2) return;
    g_b2[idx] = (idx < 8192) ? f_b[idx] : bias_b[idx - 8192];
}

__global__ void prep_W2T(const float* __restrict__ f_w, const float* __restrict__ bias_w) {
    __shared__ float tile[32][33];
    int n0 = blockIdx.x * 32, h0 = blockIdx.y * 32;
    int tx = threadIdx.x, ty = threadIdx.y;
    int n = n0 + tx, h = h0 + ty;
    float v = 0.0f;
    if (n < 8192)       v = f_w[(size_t)h * 8192 + n];
    else if (n < NOUT2) v = bias_w[h * 64 + (n - 8192)];
    tile[ty][tx] = v;
    __syncthreads();
    ((uint32_t*)g_W2T)[(size_t)(n0 + ty) * HID + h0 + tx] = f2tf(tile[tx][ty]);
}

// ---------------- activation build ----------------
__device__ __forceinline__ float knot(int j) { return -1.0f + 0.4f * (float)(j - 3); }

__global__ void build_act(const float* __restrict__ state,
                          const float* __restrict__ novelU, int B) {
    int idx = blockIdx.x * blockDim.x + threadIdx.x;
    if (idx >= B * INDIM) return;
    int b = idx / INDIM, i = idx - b * INDIM;
    float x = (i < STATE) ? state[b * STATE + i] : novelU[b * (INDIM - STATE) + (i - STATE)];
    g_x[b * INDIM + i] = x;
    g_act[(size_t)b * KACT + i] = f2tf_f(x / (1.0f + expf(-x)));
    float bb[11];
#pragma unroll
    for (int j = 0; j < 11; j++)
        bb[j] = (x >= knot(j) && x < knot(j + 1)) ? 1.0f : 0.0f;
#pragma unroll
    for (int ord = 1; ord <= 3; ord++) {
#pragma unroll
        for (int j = 0; j < 11 - 1; j++) {
            if (j >= 11 - ord) break;
            float l = (x - knot(j)) / (knot(j + ord) - knot(j));
            float r = (knot(j + ord + 1) - x) / (knot(j + ord + 1) - knot(j + 1));
            bb[j] = l * bb[j] + r * bb[j + 1];
        }
    }
    float* dst = &g_act[(size_t)b * KACT + INDIM + i * NB];
    float4 v0 = make_float4(f2tf_f(bb[0]), f2tf_f(bb[1]), f2tf_f(bb[2]), f2tf_f(bb[3]));
    float4 v1 = make_float4(f2tf_f(bb[4]), f2tf_f(bb[5]), f2tf_f(bb[6]), f2tf_f(bb[7]));
    *(float4*)dst = v0;
    *(float4*)(dst + 4) = v1;
}

// ---------------- TF32 tensor-core GEMM, cp.async double-buffered -----------
#define SA   36                 // smem row stride in u32 (144B, conflict-free ldmatrix)
#define STGB (128 * SA * 4)     // bytes per array per stage
#define XSP  130                // x-tile row stride (floats)

template<int K, bool EPI2>
__global__ __launch_bounds__(256) void mma_gemm(const float* __restrict__ A,
                                                const float* __restrict__ Bt,
                                                float* __restrict__ C,
                                                float* __restrict__ outAB,
                                                float* __restrict__ outBias,
                                                float* __restrict__ outO) {
    extern __shared__ char dynsmem[];
    uint32_t smem_addr = (uint32_t)__cvta_generic_to_shared(dynsmem);

    int tid = threadIdx.x;
    int lane = tid & 31, wid = tid >> 5;
    int row0 = blockIdx.y * 128, col0 = blockIdx.x * 128;
    int m0w = (wid & 1) * 64;
    int n0w = (wid >> 1) * 32;

    int rowA = (lane & 7) + 8 * ((lane >> 3) & 1);
    int kA   = 4 * (lane >> 4);
    int rowB = (lane & 7) + 8 * (lane >> 4);
    int kB   = 4 * ((lane >> 3) & 1);

    float acc[4][4][4];
#pragma unroll
    for (int mt = 0; mt < 4; mt++)
#pragma unroll
        for (int nt = 0; nt < 4; nt++)
#pragma unroll
            for (int j = 0; j < 4; j++) acc[mt][nt][j] = 0.0f;

    int cr = tid >> 3;
    int cc = (tid & 7) * 4;

    const int nk = K / 32;

    // stage loader
    auto load_stage = [&](int stg, int k0) {
        uint32_t dA = smem_addr + stg * 2 * STGB;
        uint32_t dB = dA + STGB;
#pragma unroll
        for (int i = 0; i < 4; i++) {
            int r = cr + i * 32;
            cpa16(dA + (uint32_t)(r * SA + cc) * 4, A  + (size_t)(row0 + r) * K + k0 + cc);
            cpa16(dB + (uint32_t)(r * SA + cc) * 4, Bt + (size_t)(col0 + r) * K + k0 + cc);
        }
    };

    load_stage(0, 0);
    cpa_commit();

    for (int it = 0; it < nk; it++) {
        int cur = it & 1;
        if (it + 1 < nk) {
            load_stage(cur ^ 1, (it + 1) * 32);
            cpa_commit();
            cpa_wait1();
        } else {
            cpa_wait0();
        }
        __syncthreads();

        uint32_t sA = smem_addr + cur * 2 * STGB;
        uint32_t sB = sA + STGB;
#pragma unroll
        for (int kk = 0; kk < 32; kk += 8) {
            uint32_t a[4][4], b[4][2];
#pragma unroll
            for (int mt = 0; mt < 4; mt++) {
                uint32_t addr = sA + (uint32_t)((m0w + mt * 16 + rowA) * SA + kk + kA) * 4;
                ldsm4(addr, a[mt][0], a[mt][1], a[mt][2], a[mt][3]);
            }
#pragma unroll
            for (int np = 0; np < 2; np++) {
                uint32_t addr = sB + (uint32_t)((n0w + np * 16 + rowB) * SA + kk + kB) * 4;
                ldsm4(addr, b[2 * np][0], b[2 * np][1], b[2 * np + 1][0], b[2 * np + 1][1]);
            }
#pragma unroll
            for (int mt = 0; mt < 4; mt++)
#pragma unroll
                for (int nt = 0; nt < 4; nt++)
                    mma_tf32(acc[mt][nt], a[mt], b[nt]);
        }
        __syncthreads();
    }

    int gid = lane >> 2, tig = lane & 3;

    // ---- matrix stores ----
#pragma unroll
    for (int mt = 0; mt < 4; mt++) {
#pragma unroll
        for (int nt = 0; nt < 4; nt++) {
            int r0r = row0 + m0w + mt * 16 + gid;
            int n   = col0 + n0w + nt * 8 + 2 * tig;
            if (!EPI2) {
                // tf32-rounded kan so gemm2's raw cp.async copy is exact
                float2 v01 = make_float2(f2tf_f(acc[mt][nt][0]), f2tf_f(acc[mt][nt][1]));
                float2 v23 = make_float2(f2tf_f(acc[mt][nt][2]), f2tf_f(acc[mt][nt][3]));
                *(float2*)(C + (size_t)r0r * HID + n)       = v01;
                *(float2*)(C + (size_t)(r0r + 8) * HID + n) = v23;
            } else {
                if (n >= NOUT2) continue;
                float b0 = g_b2[n], b1 = g_b2[n + 1];
                float2 v01 = make_float2(acc[mt][nt][0] + b0, acc[mt][nt][1] + b1);
                float2 v23 = make_float2(acc[mt][nt][2] + b0, acc[mt][nt][3] + b1);
                if (n < 8192) {
                    *(float2*)(outAB + (size_t)r0r * 8192 + n)       = v01;
                    *(float2*)(outAB + (size_t)(r0r + 8) * 8192 + n) = v23;
                } else {
                    int nb = n - 8192;
                    *(float2*)(outBias + (size_t)r0r * 64 + nb)       = v01;
                    *(float2*)(outBias + (size_t)(r0r + 8) * 64 + nb) = v23;
                }
            }
        }
    }

    // ---- fused out = (AB+f_b_tile) . x partial (full per CTA since s = col0/128) ----
    if (EPI2 && col0 < 8192) {
        float* xs  = (float*)dynsmem;            // [128][XSP]
        float* red = xs + 128 * XSP;             // [4][128]
        __syncthreads();   // smem reuse safe: mainloop done on all threads
        // stage x tile
        for (int i = tid * 4; i < 128 * 128; i += 256 * 4) {
            int r = i >> 7, u = i & 127;
            float4 v = *(const float4*)(g_x + (size_t)(row0 + r) * INDIM + u);
            xs[r * XSP + u]     = v.x;
            xs[r * XSP + u + 1] = v.y;
            xs[r * XSP + u + 2] = v.z;
            xs[r * XSP + u + 3] = v.w;
        }
        __syncthreads();

        int nw = wid >> 1;   // n-warp index 0..3
#pragma unroll
        for (int mt = 0; mt < 4; mt++) {
            int lr = m0w + mt * 16 + gid;
            float p0 = 0.0f, p1 = 0.0f;
#pragma unroll
            for (int nt = 0; nt < 4; nt++) {
                int u = n0w + nt * 8 + 2 * tig;
                float n_b0 = g_b2[col0 + u], n_b1 = g_b2[col0 + u + 1];
                float x00 = xs[lr * XSP + u],        x01 = xs[lr * XSP + u + 1];
                float x10 = xs[(lr + 8) * XSP + u],  x11 = xs[(lr + 8) * XSP + u + 1];
                p0 = fmaf(acc[mt][nt][0] + n_b0, x00, p0);
                p0 = fmaf(acc[mt][nt][1] + n_b1, x01, p0);
                p1 = fmaf(acc[mt][nt][2] + n_b0, x10, p1);
                p1 = fmaf(acc[mt][nt][3] + n_b1, x11, p1);
            }
            p0 += __shfl_xor_sync(0xffffffff, p0, 1);
            p0 += __shfl_xor_sync(0xffffffff, p0, 2);
            p1 += __shfl_xor_sync(0xffffffff, p1, 1);
            p1 += __shfl_xor_sync(0xffffffff, p1, 2);
            if (tig == 0) {
                red[nw * 128 + lr]     = p0;
                red[nw * 128 + lr + 8] = p1;
            }
        }
        __syncthreads();
        if (tid < 128) {
            float v = red[tid] + red[128 + tid] + red[256 + tid] + red[384 + tid];
            outO[(size_t)(row0 + tid) * 64 + (col0 >> 7)] = v;
        }
    }
}

// ---------------- out += bias ----------------
__global__ void add_bias(const float* __restrict__ biasOut, float* __restrict__ outO, int n) {
    int i = blockIdx.x * blockDim.x + threadIdx.x;
    if (i < n) outO[i] += biasOut[i];
}

// ---------------- launch ----------------
extern "C" void kernel_launch(void* const* d_in, const int* in_sizes, int n_in,
                              void* d_out, int out_size) {
    const float* novelU     = (const float*)d_in[0];
    const float* state      = (const float*)d_in[1];
    const float* coef       = (const float*)d_in[2];
    const float* scale_base = (const float*)d_in[3];
    const float* scale_sp   = (const float*)d_in[4];
    const float* bias_w     = (const float*)d_in[5];
    const float* bias_b     = (const float*)d_in[6];
    const float* f_w        = (const float*)d_in[7];
    const float* f_b        = (const float*)d_in[8];
    float* out = (float*)d_out;

    int B = in_sizes[0] / 64;
    if (B > BMAX) B = BMAX;

    float* outO    = out;
    float* outAB   = out + (size_t)B * 64;
    float* outBias = out + (size_t)B * 64 + (size_t)B * 8192;

    prep_W1T<<<(HID * KACT + 255) / 256, 256>>>(scale_base, scale_sp, coef);
    prep_W2T<<<dim3(NOUT2P / 32, HID / 32), dim3(32, 32)>>>(f_w, bias_w);
    prep_b2<<<(NOUT2 + 255) / 256, 256>>>(f_b, bias_b);
    build_act<<<(B * INDIM + 255) / 256, 256>>>(state, novelU, B);

    float *d_kan, *d_act, *d_W1T, *d_W2T;
    cudaGetSymbolAddress((void**)&d_kan, g_kan);
    cudaGetSymbolAddress((void**)&d_act, g_act);
    cudaGetSymbolAddress((void**)&d_W1T, g_W1T);
    cudaGetSymbolAddress((void**)&d_W2T, g_W2T);

    const int smem_bytes = 4 * STGB;   // 2 stages * (A+B) = 73728
    static bool attr_set = false;
    if (!attr_set) {
        cudaFuncSetAttribute(mma_gemm<KACT, false>,
                             cudaFuncAttributeMaxDynamicSharedMemorySize, smem_bytes);
        cudaFuncSetAttribute(mma_gemm<HID, true>,
                             cudaFuncAttributeMaxDynamicSharedMemorySize, smem_bytes);
        attr_set = true;
    }

    dim3 g1(HID / 128, B / 128);
    mma_gemm<KACT, false><<<g1, 256, smem_bytes>>>(d_act, d_W1T, d_kan, nullptr, nullptr, nullptr);

    dim3 g2(NOUT2P / 128, B / 128);
    mma_gemm<HID, true><<<g2, 256, smem_bytes>>>(d_kan, d_W2T, nullptr, outAB, outBias, outO);

    add_bias<<<(B * 64 + 255) / 256, 256>>>(outBias, outO, B * 64);
}

// round 5
// speedup vs baseline: 4.9849x; 1.2988x over previous
#include <cuda_runtime.h>
#include <cuda_fp16.h>
#include <math.h>
#include <stdint.h>

// Problem constants
#define BMAX   16384
#define INDIM  128
#define STATE  64
#define HID    1024
#define NB     8
#define KACT   (INDIM + INDIM * NB)   // 1152
#define NOUT2  (8192 + 64)            // 8256
#define NOUT2P 8320                   // padded to multiple of 128

// ---------------- scratch ----------------
__device__ float  g_x   [BMAX * INDIM];
__device__ __half g_act [BMAX * KACT];
__device__ __half g_kan [BMAX * HID];
__device__ __half g_W1T [HID * KACT];            // [o][k]
__device__ __half g_W2T [(size_t)NOUT2P * HID];  // [n][h], zero-padded rows
__device__ float  g_b2  [NOUT2];

// ---------------- helpers ----------------
__device__ __forceinline__ void ldsm4(uint32_t addr, uint32_t& r0, uint32_t& r1,
                                      uint32_t& r2, uint32_t& r3) {
    asm volatile("ldmatrix.sync.aligned.m8n8.x4.shared.b16 {%0,%1,%2,%3}, [%4];"
                 : "=r"(r0), "=r"(r1), "=r"(r2), "=r"(r3) : "r"(addr));
}

__device__ __forceinline__ void mma_f16(float* d, const uint32_t* a, const uint32_t* b) {
    asm volatile(
        "mma.sync.aligned.m16n8k16.row.col.f32.f16.f16.f32 "
        "{%0,%1,%2,%3}, {%4,%5,%6,%7}, {%8,%9}, {%0,%1,%2,%3};"
        : "+f"(d[0]), "+f"(d[1]), "+f"(d[2]), "+f"(d[3])
        : "r"(a[0]), "r"(a[1]), "r"(a[2]), "r"(a[3]), "r"(b[0]), "r"(b[1]));
}

__device__ __forceinline__ void cpa16(uint32_t smem, const void* g) {
    asm volatile("cp.async.cg.shared.global [%0], [%1], 16;" :: "r"(smem), "l"(g));
}
__device__ __forceinline__ void cpa_commit() { asm volatile("cp.async.commit_group;"); }
__device__ __forceinline__ void cpa_wait1()  { asm volatile("cp.async.wait_group 1;"); }
__device__ __forceinline__ void cpa_wait0()  { asm volatile("cp.async.wait_group 0;"); }

// ---------------- weight prep ----------------
__global__ void prep_W1T(const float* __restrict__ scale_base,
                         const float* __restrict__ scale_sp,
                         const float* __restrict__ coef) {
    int idx = blockIdx.x * blockDim.x + threadIdx.x;
    if (idx >= HID * KACT) return;
    int o = idx / KACT, k = idx - o * KACT;
    float v;
    if (k < INDIM) {
        v = scale_base[k * HID + o];
    } else {
        int kk = k - INDIM;
        int i = kk >> 3, c = kk & 7;
        v = scale_sp[i * HID + o] * coef[(i * HID + o) * NB + c];
    }
    g_W1T[idx] = __float2half(v);
}

__global__ void prep_b2(const float* __restrict__ f_b, const float* __restrict__ bias_b) {
    int idx = blockIdx.x * blockDim.x + threadIdx.x;
    if (idx >= NOUT2) return;
    g_b2[idx] = (idx < 8192) ? f_b[idx] : bias_b[idx - 8192];
}

__global__ void prep_W2T(const float* __restrict__ f_w, const float* __restrict__ bias_w) {
    __shared__ float tile[32][33];
    int n0 = blockIdx.x * 32, h0 = blockIdx.y * 32;
    int tx = threadIdx.x, ty = threadIdx.y;
    int n = n0 + tx;
    float v = 0.0f;
    if (n < 8192)       v = f_w[(size_t)(h0 + ty) * 8192 + n];
    else if (n < NOUT2) v = bias_w[(h0 + ty) * 64 + (n - 8192)];
    tile[ty][tx] = v;
    __syncthreads();
    g_W2T[(size_t)(n0 + ty) * HID + h0 + tx] = __float2half(tile[tx][ty]);
}

// ---------------- activation build ----------------
__device__ __forceinline__ float knot(int j) { return -1.0f + 0.4f * (float)(j - 3); }

__global__ void build_act(const float* __restrict__ state,
                          const float* __restrict__ novelU, int B) {
    int idx = blockIdx.x * blockDim.x + threadIdx.x;
    if (idx >= B * INDIM) return;
    int b = idx / INDIM, i = idx - b * INDIM;
    float x = (i < STATE) ? state[b * STATE + i] : novelU[b * (INDIM - STATE) + (i - STATE)];
    g_x[b * INDIM + i] = x;
    g_act[(size_t)b * KACT + i] = __float2half(x / (1.0f + expf(-x)));
    float bb[11];
#pragma unroll
    for (int j = 0; j < 11; j++)
        bb[j] = (x >= knot(j) && x < knot(j + 1)) ? 1.0f : 0.0f;
#pragma unroll
    for (int ord = 1; ord <= 3; ord++) {
#pragma unroll
        for (int j = 0; j < 11 - 1; j++) {
            if (j >= 11 - ord) break;
            float l = (x - knot(j)) / (knot(j + ord) - knot(j));
            float r = (knot(j + ord + 1) - x) / (knot(j + ord + 1) - knot(j + 1));
            bb[j] = l * bb[j] + r * bb[j + 1];
        }
    }
    __half2 h0 = __floats2half2_rn(bb[0], bb[1]);
    __half2 h1 = __floats2half2_rn(bb[2], bb[3]);
    __half2 h2 = __floats2half2_rn(bb[4], bb[5]);
    __half2 h3 = __floats2half2_rn(bb[6], bb[7]);
    uint4 pack = make_uint4(*(uint32_t*)&h0, *(uint32_t*)&h1, *(uint32_t*)&h2, *(uint32_t*)&h3);
    *(uint4*)&g_act[(size_t)b * KACT + INDIM + i * NB] = pack;
}

// ---------------- FP16 tensor-core GEMM, cp.async double-buffered -----------
#define SAH  40                  // smem row stride in halves (80B, conflict-free ldmatrix)
#define STGB (128 * SAH * 2)     // bytes per array per stage (10240)
#define XSP  130                 // x-tile row stride (floats)

template<int K, bool EPI2>
__global__ __launch_bounds__(256) void mma_gemm(const __half* __restrict__ A,
                                                const __half* __restrict__ Bt,
                                                __half* __restrict__ C,
                                                float* __restrict__ outAB,
                                                float* __restrict__ outBias,
                                                float* __restrict__ outO) {
    extern __shared__ char dynsmem[];
    uint32_t smem_addr = (uint32_t)__cvta_generic_to_shared(dynsmem);

    int tid = threadIdx.x;
    int lane = tid & 31, wid = tid >> 5;
    int row0 = blockIdx.y * 128, col0 = blockIdx.x * 128;
    int m0w = (wid & 1) * 64;
    int n0w = (wid >> 1) * 32;

    // fragment lane addressing (units: halves)
    int rowA = lane & 15;
    int kAh  = 8 * (lane >> 4);
    int rowB = (lane & 7) + 8 * (lane >> 4);
    int kBh  = 8 * ((lane >> 3) & 1);

    float acc[4][4][4];
#pragma unroll
    for (int mt = 0; mt < 4; mt++)
#pragma unroll
        for (int nt = 0; nt < 4; nt++)
#pragma unroll
            for (int j = 0; j < 4; j++) acc[mt][nt][j] = 0.0f;

    int cr = tid >> 1;            // copy row 0..127
    int cc = (tid & 1) * 16;      // copy col (halves): 2 chunks of 8 halves

    const int nk = K / 32;

    auto load_stage = [&](int stg, int k0) {
        uint32_t dA = smem_addr + stg * 2 * STGB;
        uint32_t dB = dA + STGB;
        const __half* gA = A  + (size_t)(row0 + cr) * K + k0 + cc;
        const __half* gB = Bt + (size_t)(col0 + cr) * K + k0 + cc;
        uint32_t sA = dA + (uint32_t)(cr * SAH + cc) * 2;
        uint32_t sB = dB + (uint32_t)(cr * SAH + cc) * 2;
        cpa16(sA,      gA);
        cpa16(sA + 16, gA + 8);
        cpa16(sB,      gB);
        cpa16(sB + 16, gB + 8);
    };

    load_stage(0, 0);
    cpa_commit();

    for (int it = 0; it < nk; it++) {
        int cur = it & 1;
        if (it + 1 < nk) {
            load_stage(cur ^ 1, (it + 1) * 32);
            cpa_commit();
            cpa_wait1();
        } else {
            cpa_wait0();
        }
        __syncthreads();

        uint32_t sA = smem_addr + cur * 2 * STGB;
        uint32_t sB = sA + STGB;
#pragma unroll
        for (int ks = 0; ks < 2; ks++) {            // two k16 steps per stage
            int kh = ks * 16;
            uint32_t a[4][4], b[2][4];
#pragma unroll
            for (int mt = 0; mt < 4; mt++) {
                uint32_t addr = sA + (uint32_t)((m0w + mt * 16 + rowA) * SAH + kh + kAh) * 2;
                ldsm4(addr, a[mt][0], a[mt][1], a[mt][2], a[mt][3]);
            }
#pragma unroll
            for (int ng = 0; ng < 2; ng++) {
                uint32_t addr = sB + (uint32_t)((n0w + ng * 16 + rowB) * SAH + kh + kBh) * 2;
                ldsm4(addr, b[ng][0], b[ng][1], b[ng][2], b[ng][3]);
            }
#pragma unroll
            for (int mt = 0; mt < 4; mt++)
#pragma unroll
                for (int nt = 0; nt < 4; nt++)
                    mma_f16(acc[mt][nt], a[mt], &b[nt >> 1][(nt & 1) * 2]);
        }
        __syncthreads();
    }

    int gid = lane >> 2, tig = lane & 3;

    // ---- matrix stores ----
#pragma unroll
    for (int mt = 0; mt < 4; mt++) {
#pragma unroll
        for (int nt = 0; nt < 4; nt++) {
            int r0r = row0 + m0w + mt * 16 + gid;
            int n   = col0 + n0w + nt * 8 + 2 * tig;
            if (!EPI2) {
                __half2 v01 = __floats2half2_rn(acc[mt][nt][0], acc[mt][nt][1]);
                __half2 v23 = __floats2half2_rn(acc[mt][nt][2], acc[mt][nt][3]);
                *(__half2*)(C + (size_t)r0r * HID + n)       = v01;
                *(__half2*)(C + (size_t)(r0r + 8) * HID + n) = v23;
            } else {
                if (n >= NOUT2) continue;
                float b0 = g_b2[n], b1 = g_b2[n + 1];
                float2 v01 = make_float2(acc[mt][nt][0] + b0, acc[mt][nt][1] + b1);
                float2 v23 = make_float2(acc[mt][nt][2] + b0, acc[mt][nt][3] + b1);
                if (n < 8192) {
                    *(float2*)(outAB + (size_t)r0r * 8192 + n)       = v01;
                    *(float2*)(outAB + (size_t)(r0r + 8) * 8192 + n) = v23;
                } else {
                    int nb = n - 8192;
                    *(float2*)(outBias + (size_t)r0r * 64 + nb)       = v01;
                    *(float2*)(outBias + (size_t)(r0r + 8) * 64 + nb) = v23;
                }
            }
        }
    }

    // ---- fused out = (AB + f_b tile) . x ; each 128-col tile = one s ----
    if (EPI2 && col0 < 8192) {
        float* xs  = (float*)dynsmem;            // [128][XSP]
        float* red = xs + 128 * XSP;             // [4][128]
        __syncthreads();
        for (int i = tid * 4; i < 128 * 128; i += 256 * 4) {
            int r = i >> 7, u = i & 127;
            float4 v = *(const float4*)(g_x + (size_t)(row0 + r) * INDIM + u);
            xs[r * XSP + u]     = v.x;
            xs[r * XSP + u + 1] = v.y;
            xs[r * XSP + u + 2] = v.z;
            xs[r * XSP + u + 3] = v.w;
        }
        __syncthreads();

        int nw = wid >> 1;
#pragma unroll
        for (int mt = 0; mt < 4; mt++) {
            int lr = m0w + mt * 16 + gid;
            float p0 = 0.0f, p1 = 0.0f;
#pragma unroll
            for (int nt = 0; nt < 4; nt++) {
                int u = n0w + nt * 8 + 2 * tig;
                float n_b0 = g_b2[col0 + u], n_b1 = g_b2[col0 + u + 1];
                float x00 = xs[lr * XSP + u],        x01 = xs[lr * XSP + u + 1];
                float x10 = xs[(lr + 8) * XSP + u],  x11 = xs[(lr + 8) * XSP + u + 1];
                p0 = fmaf(acc[mt][nt][0] + n_b0, x00, p0);
                p0 = fmaf(acc[mt][nt][1] + n_b1, x01, p0);
                p1 = fmaf(acc[mt][nt][2] + n_b0, x10, p1);
                p1 = fmaf(acc[mt][nt][3] + n_b1, x11, p1);
            }
            p0 += __shfl_xor_sync(0xffffffff, p0, 1);
            p0 += __shfl_xor_sync(0xffffffff, p0, 2);
            p1 += __shfl_xor_sync(0xffffffff, p1, 1);
            p1 += __shfl_xor_sync(0xffffffff, p1, 2);
            if (tig == 0) {
                red[nw * 128 + lr]     = p0;
                red[nw * 128 + lr + 8] = p1;
            }
        }
        __syncthreads();
        if (tid < 128) {
            float v = red[tid] + red[128 + tid] + red[256 + tid] + red[384 + tid];
            outO[(size_t)(row0 + tid) * 64 + (col0 >> 7)] = v;
        }
    }
}

// ---------------- out += bias ----------------
__global__ void add_bias(const float* __restrict__ biasOut, float* __restrict__ outO, int n) {
    int i = blockIdx.x * blockDim.x + threadIdx.x;
    if (i < n) outO[i] += biasOut[i];
}

// ---------------- launch ----------------
extern "C" void kernel_launch(void* const* d_in, const int* in_sizes, int n_in,
                              void* d_out, int out_size) {
    const float* novelU     = (const float*)d_in[0];
    const float* state      = (const float*)d_in[1];
    const float* coef       = (const float*)d_in[2];
    const float* scale_base = (const float*)d_in[3];
    const float* scale_sp   = (const float*)d_in[4];
    const float* bias_w     = (const float*)d_in[5];
    const float* bias_b     = (const float*)d_in[6];
    const float* f_w        = (const float*)d_in[7];
    const float* f_b        = (const float*)d_in[8];
    float* out = (float*)d_out;

    int B = in_sizes[0] / 64;
    if (B > BMAX) B = BMAX;

    float* outO    = out;
    float* outAB   = out + (size_t)B * 64;
    float* outBias = out + (size_t)B * 64 + (size_t)B * 8192;

    prep_W1T<<<(HID * KACT + 255) / 256, 256>>>(scale_base, scale_sp, coef);
    prep_W2T<<<dim3(NOUT2P / 32, HID / 32), dim3(32, 32)>>>(f_w, bias_w);
    prep_b2<<<(NOUT2 + 255) / 256, 256>>>(f_b, bias_b);
    build_act<<<(B * INDIM + 255) / 256, 256>>>(state, novelU, B);

    __half *d_kan, *d_act, *d_W1T, *d_W2T;
    cudaGetSymbolAddress((void**)&d_kan, g_kan);
    cudaGetSymbolAddress((void**)&d_act, g_act);
    cudaGetSymbolAddress((void**)&d_W1T, g_W1T);
    cudaGetSymbolAddress((void**)&d_W2T, g_W2T);

    const int smem_stage = 4 * STGB;                    // 40960
    const int smem_epi   = 128 * XSP * 4 + 4 * 128 * 4; // 68608
    const int smem_bytes = smem_epi > smem_stage ? smem_epi : smem_stage;
    static bool attr_set = false;
    if (!attr_set) {
        cudaFuncSetAttribute(mma_gemm<KACT, false>,
                             cudaFuncAttributeMaxDynamicSharedMemorySize, smem_bytes);
        cudaFuncSetAttribute(mma_gemm<HID, true>,
                             cudaFuncAttributeMaxDynamicSharedMemorySize, smem_bytes);
        attr_set = true;
    }

    dim3 g1(HID / 128, B / 128);
    mma_gemm<KACT, false><<<g1, 256, smem_bytes>>>(d_act, d_W1T, d_kan, nullptr, nullptr, nullptr);

    dim3 g2(NOUT2P / 128, B / 128);
    mma_gemm<HID, true><<<g2, 256, smem_bytes>>>(d_kan, d_W2T, nullptr, outAB, outBias, outO);

    add_bias<<<(B * 64 + 255) / 256, 256>>>(outBias, outO, B * 64);
}

// round 6
// speedup vs baseline: 5.2615x; 1.0555x over previous
#include <cuda_runtime.h>
#include <cuda_fp16.h>
#include <math.h>
#include <stdint.h>

// Problem constants
#define BMAX   16384
#define INDIM  128
#define STATE  64
#define HID    1024
#define NB     8
#define KACT   (INDIM + INDIM * NB)   // 1152
#define NOUT2  (8192 + 64)            // 8256
#define NOUT2P 8448                   // padded to multiple of 256

// ---------------- scratch ----------------
__device__ float  g_x   [BMAX * INDIM];
__device__ __half g_act [BMAX * KACT];
__device__ __half g_kan [BMAX * HID];
__device__ __half g_W1T [HID * KACT];            // [o][k]
__device__ __half g_W2T [(size_t)NOUT2P * HID];  // [n][h], zero-padded rows
__device__ float  g_b2  [NOUT2];

// ---------------- helpers ----------------
__device__ __forceinline__ void ldsm4(uint32_t addr, uint32_t& r0, uint32_t& r1,
                                      uint32_t& r2, uint32_t& r3) {
    asm volatile("ldmatrix.sync.aligned.m8n8.x4.shared.b16 {%0,%1,%2,%3}, [%4];"
                 : "=r"(r0), "=r"(r1), "=r"(r2), "=r"(r3) : "r"(addr));
}

__device__ __forceinline__ void mma_f16(float* d, const uint32_t* a, const uint32_t* b) {
    asm volatile(
        "mma.sync.aligned.m16n8k16.row.col.f32.f16.f16.f32 "
        "{%0,%1,%2,%3}, {%4,%5,%6,%7}, {%8,%9}, {%0,%1,%2,%3};"
        : "+f"(d[0]), "+f"(d[1]), "+f"(d[2]), "+f"(d[3])
        : "r"(a[0]), "r"(a[1]), "r"(a[2]), "r"(a[3]), "r"(b[0]), "r"(b[1]));
}

__device__ __forceinline__ void cpa16(uint32_t smem, const void* g) {
    asm volatile("cp.async.cg.shared.global [%0], [%1], 16;" :: "r"(smem), "l"(g));
}
__device__ __forceinline__ void cpa_commit() { asm volatile("cp.async.commit_group;"); }
__device__ __forceinline__ void cpa_wait1()  { asm volatile("cp.async.wait_group 1;"); }

// ---------------- weight prep ----------------
__global__ void prep_W1T(const float* __restrict__ scale_base,
                         const float* __restrict__ scale_sp,
                         const float* __restrict__ coef) {
    int idx = blockIdx.x * blockDim.x + threadIdx.x;
    if (idx >= HID * KACT) return;
    int o = idx / KACT, k = idx - o * KACT;
    float v;
    if (k < INDIM) {
        v = scale_base[k * HID + o];
    } else {
        int kk = k - INDIM;
        int i = kk >> 3, c = kk & 7;
        v = scale_sp[i * HID + o] * coef[(i * HID + o) * NB + c];
    }
    g_W1T[idx] = __float2half(v);
}

__global__ void prep_b2(const float* __restrict__ f_b, const float* __restrict__ bias_b) {
    int idx = blockIdx.x * blockDim.x + threadIdx.x;
    if (idx >= NOUT2) return;
    g_b2[idx] = (idx < 8192) ? f_b[idx] : bias_b[idx - 8192];
}

__global__ void prep_W2T(const float* __restrict__ f_w, const float* __restrict__ bias_w) {
    __shared__ float tile[32][33];
    int n0 = blockIdx.x * 32, h0 = blockIdx.y * 32;
    int tx = threadIdx.x, ty = threadIdx.y;
    int n = n0 + tx;
    float v = 0.0f;
    if (n < 8192)       v = f_w[(size_t)(h0 + ty) * 8192 + n];
    else if (n < NOUT2) v = bias_w[(h0 + ty) * 64 + (n - 8192)];
    tile[ty][tx] = v;
    __syncthreads();
    g_W2T[(size_t)(n0 + ty) * HID + h0 + tx] = __float2half(tile[tx][ty]);
}

// ---------------- activation build ----------------
__device__ __forceinline__ float knot(int j) { return -1.0f + 0.4f * (float)(j - 3); }

__global__ void build_act(const float* __restrict__ state,
                          const float* __restrict__ novelU, int B) {
    int idx = blockIdx.x * blockDim.x + threadIdx.x;
    if (idx >= B * INDIM) return;
    int b = idx / INDIM, i = idx - b * INDIM;
    float x = (i < STATE) ? state[b * STATE + i] : novelU[b * (INDIM - STATE) + (i - STATE)];
    g_x[b * INDIM + i] = x;
    g_act[(size_t)b * KACT + i] = __float2half(x / (1.0f + expf(-x)));
    float bb[11];
#pragma unroll
    for (int j = 0; j < 11; j++)
        bb[j] = (x >= knot(j) && x < knot(j + 1)) ? 1.0f : 0.0f;
#pragma unroll
    for (int ord = 1; ord <= 3; ord++) {
#pragma unroll
        for (int j = 0; j < 11 - 1; j++) {
            if (j >= 11 - ord) break;
            float l = (x - knot(j)) / (knot(j + ord) - knot(j));
            float r = (knot(j + ord + 1) - x) / (knot(j + ord + 1) - knot(j + 1));
            bb[j] = l * bb[j] + r * bb[j + 1];
        }
    }
    __half2 h0 = __floats2half2_rn(bb[0], bb[1]);
    __half2 h1 = __floats2half2_rn(bb[2], bb[3]);
    __half2 h2 = __floats2half2_rn(bb[4], bb[5]);
    __half2 h3 = __floats2half2_rn(bb[6], bb[7]);
    uint4 pack = make_uint4(*(uint32_t*)&h0, *(uint32_t*)&h1, *(uint32_t*)&h2, *(uint32_t*)&h3);
    *(uint4*)&g_act[(size_t)b * KACT + INDIM + i * NB] = pack;
}

// ---------------- FP16 tensor-core GEMM ------------------------------------
// CTA tile 128x256, 512 threads (16 warps, warp tile 64x32), 3-stage cp.async,
// ONE __syncthreads per K=32 chunk.
#define SAH   40                          // smem row stride (halves); conflict-free ldmatrix
#define STG_H ((128 + 256) * SAH)         // halves per stage
#define STGB  (STG_H * 2)                 // 30720 bytes per stage
#define XSP   130                         // x-tile row stride (floats)

template<int K, bool EPI2>
__global__ __launch_bounds__(512) void mma_gemm(const __half* __restrict__ A,
                                                const __half* __restrict__ Bt,
                                                __half* __restrict__ C,
                                                float* __restrict__ outAB,
                                                float* __restrict__ outBias,
                                                float* __restrict__ outO) {
    extern __shared__ char dynsmem[];
    uint32_t smem_addr = (uint32_t)__cvta_generic_to_shared(dynsmem);

    int tid = threadIdx.x;
    int lane = tid & 31, wid = tid >> 5;        // wid 0..15
    int row0 = blockIdx.y * 128, col0 = blockIdx.x * 256;
    int m0w = (wid & 1) * 64;                   // 2 m-warps
    int n0w = (wid >> 1) * 32;                  // 8 n-warps -> 256 cols

    // fragment lane addressing (units: halves)
    int rowA = lane & 15;
    int kAh  = 8 * (lane >> 4);
    int rowB = (lane & 7) + 8 * (lane >> 4);
    int kBh  = 8 * ((lane >> 3) & 1);

    float acc[4][4][4];
#pragma unroll
    for (int mt = 0; mt < 4; mt++)
#pragma unroll
        for (int nt = 0; nt < 4; nt++)
#pragma unroll
            for (int j = 0; j < 4; j++) acc[mt][nt][j] = 0.0f;

    // copy mapping: 512 threads, 16B chunks; A: 128 rows x 4 chunks, B: 256 rows x 4 chunks
    int crow = tid >> 2;            // 0..127
    int coff = (tid & 3) * 8;       // halves

    const int nk = K / 32;

    auto load_stage = [&](int stg, int k0) {
        uint32_t base = smem_addr + stg * STGB;
        uint32_t bbase = base + 128 * SAH * 2;
        cpa16(base + (uint32_t)(crow * SAH + coff) * 2,
              A + (size_t)(row0 + crow) * K + k0 + coff);
        cpa16(bbase + (uint32_t)(crow * SAH + coff) * 2,
              Bt + (size_t)(col0 + crow) * K + k0 + coff);
        cpa16(bbase + (uint32_t)((crow + 128) * SAH + coff) * 2,
              Bt + (size_t)(col0 + crow + 128) * K + k0 + coff);
    };

    load_stage(0, 0);
    cpa_commit();
    load_stage(1, 32);
    cpa_commit();

    for (int it = 0; it < nk; it++) {
        int cur = it % 3;
        cpa_wait1();          // stage cur complete (<=1 group pending)
        __syncthreads();      // data visible + prior reads of overwrite-slot done
        int nx = it + 2;
        if (nx < nk) load_stage(nx % 3, nx * 32);
        cpa_commit();         // always commit to keep group numbering

        uint32_t sA = smem_addr + cur * STGB;
        uint32_t sB = sA + 128 * SAH * 2;
#pragma unroll
        for (int ks = 0; ks < 2; ks++) {
            int kh = ks * 16;
            uint32_t a[4][4], b[2][4];
#pragma unroll
            for (int mt = 0; mt < 4; mt++) {
                uint32_t addr = sA + (uint32_t)((m0w + mt * 16 + rowA) * SAH + kh + kAh) * 2;
                ldsm4(addr, a[mt][0], a[mt][1], a[mt][2], a[mt][3]);
            }
#pragma unroll
            for (int ng = 0; ng < 2; ng++) {
                uint32_t addr = sB + (uint32_t)((n0w + ng * 16 + rowB) * SAH + kh + kBh) * 2;
                ldsm4(addr, b[ng][0], b[ng][1], b[ng][2], b[ng][3]);
            }
#pragma unroll
            for (int mt = 0; mt < 4; mt++)
#pragma unroll
                for (int nt = 0; nt < 4; nt++)
                    mma_f16(acc[mt][nt], a[mt], &b[nt >> 1][(nt & 1) * 2]);
        }
    }

    int gid = lane >> 2, tig = lane & 3;

    // ---- matrix stores ----
#pragma unroll
    for (int mt = 0; mt < 4; mt++) {
#pragma unroll
        for (int nt = 0; nt < 4; nt++) {
            int r0r = row0 + m0w + mt * 16 + gid;
            int n   = col0 + n0w + nt * 8 + 2 * tig;
            if (!EPI2) {
                __half2 v01 = __floats2half2_rn(acc[mt][nt][0], acc[mt][nt][1]);
                __half2 v23 = __floats2half2_rn(acc[mt][nt][2], acc[mt][nt][3]);
                *(__half2*)(C + (size_t)r0r * HID + n)       = v01;
                *(__half2*)(C + (size_t)(r0r + 8) * HID + n) = v23;
            } else {
                if (n >= NOUT2) continue;
                float b0 = g_b2[n], b1 = g_b2[n + 1];
                float2 v01 = make_float2(acc[mt][nt][0] + b0, acc[mt][nt][1] + b1);
                float2 v23 = make_float2(acc[mt][nt][2] + b0, acc[mt][nt][3] + b1);
                if (n < 8192) {
                    *(float2*)(outAB + (size_t)r0r * 8192 + n)       = v01;
                    *(float2*)(outAB + (size_t)(r0r + 8) * 8192 + n) = v23;
                } else {
                    int nb = n - 8192;
                    *(float2*)(outBias + (size_t)r0r * 64 + nb)       = v01;
                    *(float2*)(outBias + (size_t)(r0r + 8) * 64 + nb) = v23;
                }
            }
        }
    }

    // ---- fused out = (AB + f_b tile) . x ; 256-col tile = 2 s values ----
    if (EPI2 && col0 < 8192) {
        float* xs  = (float*)dynsmem;            // [128][XSP]
        float* red = xs + 128 * XSP;             // [4 j][2 s][128 rows]
        __syncthreads();
        for (int i = tid * 4; i < 128 * 128; i += 512 * 4) {
            int r = i >> 7, u = i & 127;
            float4 v = *(const float4*)(g_x + (size_t)(row0 + r) * INDIM + u);
            xs[r * XSP + u]     = v.x;
            xs[r * XSP + u + 1] = v.y;
            xs[r * XSP + u + 2] = v.z;
            xs[r * XSP + u + 3] = v.w;
        }
        __syncthreads();

        int g = wid >> 1;          // n-group 0..7
        int sl = g >> 2;           // s_local 0/1
        int jj = g & 3;            // reduction slot
#pragma unroll
        for (int mt = 0; mt < 4; mt++) {
            int lr = m0w + mt * 16 + gid;
            float p0 = 0.0f, p1 = 0.0f;
#pragma unroll
            for (int nt = 0; nt < 4; nt++) {
                int u  = n0w + nt * 8 + 2 * tig;    // 0..255
                int ux = u & 127;
                float n_b0 = g_b2[col0 + u], n_b1 = g_b2[col0 + u + 1];
                float x00 = xs[lr * XSP + ux],       x01 = xs[lr * XSP + ux + 1];
                float x10 = xs[(lr + 8) * XSP + ux], x11 = xs[(lr + 8) * XSP + ux + 1];
                p0 = fmaf(acc[mt][nt][0] + n_b0, x00, p0);
                p0 = fmaf(acc[mt][nt][1] + n_b1, x01, p0);
                p1 = fmaf(acc[mt][nt][2] + n_b0, x10, p1);
                p1 = fmaf(acc[mt][nt][3] + n_b1, x11, p1);
            }
            p0 += __shfl_xor_sync(0xffffffff, p0, 1);
            p0 += __shfl_xor_sync(0xffffffff, p0, 2);
            p1 += __shfl_xor_sync(0xffffffff, p1, 1);
            p1 += __shfl_xor_sync(0xffffffff, p1, 2);
            if (tig == 0) {
                red[(jj * 2 + sl) * 128 + lr]     = p0;
                red[(jj * 2 + sl) * 128 + lr + 8] = p1;
            }
        }
        __syncthreads();
        if (tid < 256) {
            int srow = tid & 127, s_l = tid >> 7;
            float v = red[(0 * 2 + s_l) * 128 + srow] + red[(1 * 2 + s_l) * 128 + srow]
                    + red[(2 * 2 + s_l) * 128 + srow] + red[(3 * 2 + s_l) * 128 + srow];
            outO[(size_t)(row0 + srow) * 64 + (col0 >> 7) + s_l] = v;
        }
    }
}

// ---------------- out += bias ----------------
__global__ void add_bias(const float* __restrict__ biasOut, float* __restrict__ outO, int n) {
    int i = blockIdx.x * blockDim.x + threadIdx.x;
    if (i < n) outO[i] += biasOut[i];
}

// ---------------- launch ----------------
extern "C" void kernel_launch(void* const* d_in, const int* in_sizes, int n_in,
                              void* d_out, int out_size) {
    const float* novelU     = (const float*)d_in[0];
    const float* state      = (const float*)d_in[1];
    const float* coef       = (const float*)d_in[2];
    const float* scale_base = (const float*)d_in[3];
    const float* scale_sp   = (const float*)d_in[4];
    const float* bias_w     = (const float*)d_in[5];
    const float* bias_b     = (const float*)d_in[6];
    const float* f_w        = (const float*)d_in[7];
    const float* f_b        = (const float*)d_in[8];
    float* out = (float*)d_out;

    int B = in_sizes[0] / 64;
    if (B > BMAX) B = BMAX;

    float* outO    = out;
    float* outAB   = out + (size_t)B * 64;
    float* outBias = out + (size_t)B * 64 + (size_t)B * 8192;

    prep_W1T<<<(HID * KACT + 255) / 256, 256>>>(scale_base, scale_sp, coef);
    prep_W2T<<<dim3(NOUT2P / 32, HID / 32), dim3(32, 32)>>>(f_w, bias_w);
    prep_b2<<<(NOUT2 + 255) / 256, 256>>>(f_b, bias_b);
    build_act<<<(B * INDIM + 255) / 256, 256>>>(state, novelU, B);

    __half *d_kan, *d_act, *d_W1T, *d_W2T;
    cudaGetSymbolAddress((void**)&d_kan, g_kan);
    cudaGetSymbolAddress((void**)&d_act, g_act);
    cudaGetSymbolAddress((void**)&d_W1T, g_W1T);
    cudaGetSymbolAddress((void**)&d_W2T, g_W2T);

    const int smem_stage = 3 * STGB;                        // 92160
    const int smem_epi   = 128 * XSP * 4 + 8 * 128 * 4;     // 70656
    const int smem_bytes = smem_epi > smem_stage ? smem_epi : smem_stage;
    static bool attr_set = false;
    if (!attr_set) {
        cudaFuncSetAttribute(mma_gemm<KACT, false>,
                             cudaFuncAttributeMaxDynamicSharedMemorySize, smem_bytes);
        cudaFuncSetAttribute(mma_gemm<HID, true>,
                             cudaFuncAttributeMaxDynamicSharedMemorySize, smem_bytes);
        attr_set = true;
    }

    dim3 g1(HID / 256, B / 128);
    mma_gemm<KACT, false><<<g1, 512, smem_bytes>>>(d_act, d_W1T, d_kan, nullptr, nullptr, nullptr);

    dim3 g2(NOUT2P / 256, B / 128);
    mma_gemm<HID, true><<<g2, 512, smem_bytes>>>(d_kan, d_W2T, nullptr, outAB, outBias, outO);

    add_bias<<<(B * 64 + 255) / 256, 256>>>(outBias, outO, B * 64);
}

// round 7
// speedup vs baseline: 6.0801x; 1.1556x over previous
#include <cuda_runtime.h>
#include <cuda_fp16.h>
#include <math.h>
#include <stdint.h>

// Problem constants
#define BMAX   16384
#define INDIM  128
#define STATE  64
#define HID    1024
#define NB     8
#define KACT   (INDIM + INDIM * NB)   // 1152
#define NOUT2  (8192 + 64)            // 8256
#define NOUT2P 8448                   // padded to multiple of 256

// ---------------- scratch ----------------
__device__ float  g_x   [BMAX * INDIM];
__device__ __half g_act [BMAX * KACT];
__device__ __half g_kan [BMAX * HID];
__device__ __half g_W1T [HID * KACT];            // [o][k]
__device__ __half g_W2T [(size_t)NOUT2P * HID];  // [n][h], zero-padded rows
__device__ float  g_b2  [NOUT2];

// ---------------- helpers ----------------
__device__ __forceinline__ void ldsm4(uint32_t addr, uint32_t& r0, uint32_t& r1,
                                      uint32_t& r2, uint32_t& r3) {
    asm volatile("ldmatrix.sync.aligned.m8n8.x4.shared.b16 {%0,%1,%2,%3}, [%4];"
                 : "=r"(r0), "=r"(r1), "=r"(r2), "=r"(r3) : "r"(addr));
}

__device__ __forceinline__ void mma_f16(float* d, const uint32_t* a, const uint32_t* b) {
    asm volatile(
        "mma.sync.aligned.m16n8k16.row.col.f32.f16.f16.f32 "
        "{%0,%1,%2,%3}, {%4,%5,%6,%7}, {%8,%9}, {%0,%1,%2,%3};"
        : "+f"(d[0]), "+f"(d[1]), "+f"(d[2]), "+f"(d[3])
        : "r"(a[0]), "r"(a[1]), "r"(a[2]), "r"(a[3]), "r"(b[0]), "r"(b[1]));
}

__device__ __forceinline__ void cpa16(uint32_t smem, const void* g) {
    asm volatile("cp.async.cg.shared.global [%0], [%1], 16;" :: "r"(smem), "l"(g));
}
__device__ __forceinline__ void cpa_commit() { asm volatile("cp.async.commit_group;"); }
__device__ __forceinline__ void cpa_wait1()  { asm volatile("cp.async.wait_group 1;"); }

// ---------------- merged prep kernel ----------------
// blocks [0, NB_W2T): W2T transpose tiles; [NB_W2T, +NB_W1T): W1T; last: b2
#define NB_W2T ((NOUT2P / 32) * (HID / 32))         // 264*32 = 8448
#define NB_W1T ((HID * KACT + 255) / 256)           // 4608
#define NB_B2  ((NOUT2 + 255) / 256)                // 33

__global__ __launch_bounds__(256) void prep_all(const float* __restrict__ scale_base,
                                                const float* __restrict__ scale_sp,
                                                const float* __restrict__ coef,
                                                const float* __restrict__ f_w,
                                                const float* __restrict__ bias_w,
                                                const float* __restrict__ f_b,
                                                const float* __restrict__ bias_b) {
    int bx = blockIdx.x;
    int tid = threadIdx.x;
    if (bx < NB_W2T) {
        // transpose [HID][NOUT2-ish] -> W2T[NOUT2P][HID] tile 32x32
        __shared__ float tile[32][33];
        int tileN = bx % (NOUT2P / 32), tileH = bx / (NOUT2P / 32);
        int n0 = tileN * 32, h0 = tileH * 32;
        int tx = tid & 31, ty0 = tid >> 5;   // 8 rows per pass, 4 passes
#pragma unroll
        for (int p = 0; p < 4; p++) {
            int ty = ty0 + p * 8;
            int n = n0 + tx;
            float v = 0.0f;
            if (n < 8192)       v = f_w[(size_t)(h0 + ty) * 8192 + n];
            else if (n < NOUT2) v = bias_w[(h0 + ty) * 64 + (n - 8192)];
            tile[ty][tx] = v;
        }
        __syncthreads();
#pragma unroll
        for (int p = 0; p < 4; p++) {
            int ty = ty0 + p * 8;
            g_W2T[(size_t)(n0 + ty) * HID + h0 + tx] = __float2half(tile[tx][ty]);
        }
    } else if (bx < NB_W2T + NB_W1T) {
        int idx = (bx - NB_W2T) * 256 + tid;
        if (idx >= HID * KACT) return;
        int o = idx / KACT, k = idx - o * KACT;
        float v;
        if (k < INDIM) {
            v = scale_base[k * HID + o];
        } else {
            int kk = k - INDIM;
            int i = kk >> 3, c = kk & 7;
            v = scale_sp[i * HID + o] * coef[(i * HID + o) * NB + c];
        }
        g_W1T[idx] = __float2half(v);
    } else {
        int idx = (bx - NB_W2T - NB_W1T) * 256 + tid;
        if (idx >= NOUT2) return;
        g_b2[idx] = (idx < 8192) ? f_b[idx] : bias_b[idx - 8192];
    }
}

// ---------------- activation build ----------------
__device__ __forceinline__ float knot(int j) { return -1.0f + 0.4f * (float)(j - 3); }

__global__ void build_act(const float* __restrict__ state,
                          const float* __restrict__ novelU, int B) {
    int idx = blockIdx.x * blockDim.x + threadIdx.x;
    if (idx >= B * INDIM) return;
    int b = idx / INDIM, i = idx - b * INDIM;
    float x = (i < STATE) ? state[b * STATE + i] : novelU[b * (INDIM - STATE) + (i - STATE)];
    g_x[b * INDIM + i] = x;
    g_act[(size_t)b * KACT + i] = __float2half(x / (1.0f + expf(-x)));
    float bb[11];
#pragma unroll
    for (int j = 0; j < 11; j++)
        bb[j] = (x >= knot(j) && x < knot(j + 1)) ? 1.0f : 0.0f;
#pragma unroll
    for (int ord = 1; ord <= 3; ord++) {
#pragma unroll
        for (int j = 0; j < 11 - 1; j++) {
            if (j >= 11 - ord) break;
            float l = (x - knot(j)) / (knot(j + ord) - knot(j));
            float r = (knot(j + ord + 1) - x) / (knot(j + ord + 1) - knot(j + 1));
            bb[j] = l * bb[j] + r * bb[j + 1];
        }
    }
    __half2 h0 = __floats2half2_rn(bb[0], bb[1]);
    __half2 h1 = __floats2half2_rn(bb[2], bb[3]);
    __half2 h2 = __floats2half2_rn(bb[4], bb[5]);
    __half2 h3 = __floats2half2_rn(bb[6], bb[7]);
    uint4 pack = make_uint4(*(uint32_t*)&h0, *(uint32_t*)&h1, *(uint32_t*)&h2, *(uint32_t*)&h3);
    *(uint4*)&g_act[(size_t)b * KACT + INDIM + i * NB] = pack;
}

// ---------------- FP16 tensor-core GEMM ------------------------------------
// CTA tile 128x256, 512 threads (16 warps, warp tile 64x32), KC=64,
// 3-stage cp.async ring, ONE __syncthreads per K=64 chunk.
#define KC    64
#define SAH   72                          // smem row stride (halves); 144B, conflict-free
#define STG_H ((128 + 256) * SAH)
#define STGB  (STG_H * 2)                 // 55296 bytes per stage
#define XSP   130                         // x-tile row stride (floats)

template<int K, bool EPI2>
__global__ __launch_bounds__(512) void mma_gemm(const __half* __restrict__ A,
                                                const __half* __restrict__ Bt,
                                                __half* __restrict__ C,
                                                float* __restrict__ outAB,
                                                float* __restrict__ outBias,
                                                float* __restrict__ outO) {
    extern __shared__ char dynsmem[];
    uint32_t smem_addr = (uint32_t)__cvta_generic_to_shared(dynsmem);

    int tid = threadIdx.x;
    int lane = tid & 31, wid = tid >> 5;        // wid 0..15
    int row0 = blockIdx.y * 128, col0 = blockIdx.x * 256;
    int m0w = (wid & 1) * 64;                   // 2 m-warps
    int n0w = (wid >> 1) * 32;                  // 8 n-warps

    // fragment lane addressing (units: halves)
    int rowA = lane & 15;
    int kAh  = 8 * (lane >> 4);
    int rowB = (lane & 7) + 8 * (lane >> 4);
    int kBh  = 8 * ((lane >> 3) & 1);

    float acc[4][4][4];
#pragma unroll
    for (int mt = 0; mt < 4; mt++)
#pragma unroll
        for (int nt = 0; nt < 4; nt++)
#pragma unroll
            for (int j = 0; j < 4; j++) acc[mt][nt][j] = 0.0f;

    // copy mapping: 384 rows x 128B per stage = 3072 x 16B chunks; 6 per thread
    const int nk = K / KC;

    auto load_stage = [&](int stg, int k0) {
        uint32_t base = smem_addr + stg * STGB;
#pragma unroll
        for (int c = 0; c < 6; c++) {
            int ch  = tid + c * 512;         // 0..3071
            int r   = ch >> 3;               // 0..383
            int off = (ch & 7) * 8;          // halves within 64
            const __half* src = (r < 128)
                ? A  + (size_t)(row0 + r) * K + k0 + off
                : Bt + (size_t)(col0 + (r - 128)) * K + k0 + off;
            cpa16(base + (uint32_t)(r * SAH + off) * 2, src);
        }
    };

    load_stage(0, 0);
    cpa_commit();
    load_stage(1, KC);
    cpa_commit();

    for (int it = 0; it < nk; it++) {
        int cur = it % 3;
        cpa_wait1();
        __syncthreads();
        int nx = it + 2;
        if (nx < nk) load_stage(nx % 3, nx * KC);
        cpa_commit();

        uint32_t sA = smem_addr + cur * STGB;
        uint32_t sB = sA + 128 * SAH * 2;
#pragma unroll
        for (int ks = 0; ks < 4; ks++) {
            int kh = ks * 16;
            uint32_t a[4][4], b[2][4];
#pragma unroll
            for (int mt = 0; mt < 4; mt++) {
                uint32_t addr = sA + (uint32_t)((m0w + mt * 16 + rowA) * SAH + kh + kAh) * 2;
                ldsm4(addr, a[mt][0], a[mt][1], a[mt][2], a[mt][3]);
            }
#pragma unroll
            for (int ng = 0; ng < 2; ng++) {
                uint32_t addr = sB + (uint32_t)((n0w + ng * 16 + rowB) * SAH + kh + kBh) * 2;
                ldsm4(addr, b[ng][0], b[ng][1], b[ng][2], b[ng][3]);
            }
#pragma unroll
            for (int mt = 0; mt < 4; mt++)
#pragma unroll
                for (int nt = 0; nt < 4; nt++)
                    mma_f16(acc[mt][nt], a[mt], &b[nt >> 1][(nt & 1) * 2]);
        }
    }

    int gid = lane >> 2, tig = lane & 3;

    // ---- matrix stores ----
#pragma unroll
    for (int mt = 0; mt < 4; mt++) {
#pragma unroll
        for (int nt = 0; nt < 4; nt++) {
            int r0r = row0 + m0w + mt * 16 + gid;
            int n   = col0 + n0w + nt * 8 + 2 * tig;
            if (!EPI2) {
                __half2 v01 = __floats2half2_rn(acc[mt][nt][0], acc[mt][nt][1]);
                __half2 v23 = __floats2half2_rn(acc[mt][nt][2], acc[mt][nt][3]);
                *(__half2*)(C + (size_t)r0r * HID + n)       = v01;
                *(__half2*)(C + (size_t)(r0r + 8) * HID + n) = v23;
            } else {
                if (n >= NOUT2) continue;
                float b0 = g_b2[n], b1 = g_b2[n + 1];
                float2 v01 = make_float2(acc[mt][nt][0] + b0, acc[mt][nt][1] + b1);
                float2 v23 = make_float2(acc[mt][nt][2] + b0, acc[mt][nt][3] + b1);
                if (n < 8192) {
                    *(float2*)(outAB + (size_t)r0r * 8192 + n)       = v01;
                    *(float2*)(outAB + (size_t)(r0r + 8) * 8192 + n) = v23;
                } else {
                    int nb = n - 8192;
                    *(float2*)(outBias + (size_t)r0r * 64 + nb)       = v01;
                    *(float2*)(outBias + (size_t)(r0r + 8) * 64 + nb) = v23;
                }
            }
        }
    }

    // ---- fused out = (AB + f_b tile) . x ; 256-col tile = 2 s values ----
    if (EPI2 && col0 < 8192) {
        float* xs  = (float*)dynsmem;            // [128][XSP]
        float* red = xs + 128 * XSP;             // [4 j][2 s][128 rows]
        __syncthreads();
        for (int i = tid * 4; i < 128 * 128; i += 512 * 4) {
            int r = i >> 7, u = i & 127;
            float4 v = *(const float4*)(g_x + (size_t)(row0 + r) * INDIM + u);
            xs[r * XSP + u]     = v.x;
            xs[r * XSP + u + 1] = v.y;
            xs[r * XSP + u + 2] = v.z;
            xs[r * XSP + u + 3] = v.w;
        }
        __syncthreads();

        int g = wid >> 1;          // n-group 0..7
        int sl = g >> 2;           // s_local 0/1
        int jj = g & 3;            // reduction slot
#pragma unroll
        for (int mt = 0; mt < 4; mt++) {
            int lr = m0w + mt * 16 + gid;
            float p0 = 0.0f, p1 = 0.0f;
#pragma unroll
            for (int nt = 0; nt < 4; nt++) {
                int u  = n0w + nt * 8 + 2 * tig;
                int ux = u & 127;
                float n_b0 = g_b2[col0 + u], n_b1 = g_b2[col0 + u + 1];
                float x00 = xs[lr * XSP + ux],       x01 = xs[lr * XSP + ux + 1];
                float x10 = xs[(lr + 8) * XSP + ux], x11 = xs[(lr + 8) * XSP + ux + 1];
                p0 = fmaf(acc[mt][nt][0] + n_b0, x00, p0);
                p0 = fmaf(acc[mt][nt][1] + n_b1, x01, p0);
                p1 = fmaf(acc[mt][nt][2] + n_b0, x10, p1);
                p1 = fmaf(acc[mt][nt][3] + n_b1, x11, p1);
            }
            p0 += __shfl_xor_sync(0xffffffff, p0, 1);
            p0 += __shfl_xor_sync(0xffffffff, p0, 2);
            p1 += __shfl_xor_sync(0xffffffff, p1, 1);
            p1 += __shfl_xor_sync(0xffffffff, p1, 2);
            if (tig == 0) {
                red[(jj * 2 + sl) * 128 + lr]     = p0;
                red[(jj * 2 + sl) * 128 + lr + 8] = p1;
            }
        }
        __syncthreads();
        if (tid < 256) {
            int srow = tid & 127, s_l = tid >> 7;
            float v = red[(0 * 2 + s_l) * 128 + srow] + red[(1 * 2 + s_l) * 128 + srow]
                    + red[(2 * 2 + s_l) * 128 + srow] + red[(3 * 2 + s_l) * 128 + srow];
            outO[(size_t)(row0 + srow) * 64 + (col0 >> 7) + s_l] = v;
        }
    }
}

// ---------------- out += bias ----------------
__global__ void add_bias(const float* __restrict__ biasOut, float* __restrict__ outO, int n) {
    int i = blockIdx.x * blockDim.x + threadIdx.x;
    if (i < n) outO[i] += biasOut[i];
}

// ---------------- launch ----------------
extern "C" void kernel_launch(void* const* d_in, const int* in_sizes, int n_in,
                              void* d_out, int out_size) {
    const float* novelU     = (const float*)d_in[0];
    const float* state      = (const float*)d_in[1];
    const float* coef       = (const float*)d_in[2];
    const float* scale_base = (const float*)d_in[3];
    const float* scale_sp   = (const float*)d_in[4];
    const float* bias_w     = (const float*)d_in[5];
    const float* bias_b     = (const float*)d_in[6];
    const float* f_w        = (const float*)d_in[7];
    const float* f_b        = (const float*)d_in[8];
    float* out = (float*)d_out;

    int B = in_sizes[0] / 64;
    if (B > BMAX) B = BMAX;

    float* outO    = out;
    float* outAB   = out + (size_t)B * 64;
    float* outBias = out + (size_t)B * 64 + (size_t)B * 8192;

    prep_all<<<NB_W2T + NB_W1T + NB_B2, 256>>>(scale_base, scale_sp, coef,
                                               f_w, bias_w, f_b, bias_b);
    build_act<<<(B * INDIM + 255) / 256, 256>>>(state, novelU, B);

    __half *d_kan, *d_act, *d_W1T, *d_W2T;
    cudaGetSymbolAddress((void**)&d_kan, g_kan);
    cudaGetSymbolAddress((void**)&d_act, g_act);
    cudaGetSymbolAddress((void**)&d_W1T, g_W1T);
    cudaGetSymbolAddress((void**)&d_W2T, g_W2T);

    const int smem_stage = 3 * STGB;                        // 165888
    const int smem_epi   = 128 * XSP * 4 + 8 * 128 * 4;     // 70656
    const int smem_bytes = smem_epi > smem_stage ? smem_epi : smem_stage;
    static bool attr_set = false;
    if (!attr_set) {
        cudaFuncSetAttribute(mma_gemm<KACT, false>,
                             cudaFuncAttributeMaxDynamicSharedMemorySize, smem_bytes);
        cudaFuncSetAttribute(mma_gemm<HID, true>,
                             cudaFuncAttributeMaxDynamicSharedMemorySize, smem_bytes);
        attr_set = true;
    }

    dim3 g1(HID / 256, B / 128);
    mma_gemm<KACT, false><<<g1, 512, smem_bytes>>>(d_act, d_W1T, d_kan, nullptr, nullptr, nullptr);

    dim3 g2(NOUT2P / 256, B / 128);
    mma_gemm<HID, true><<<g2, 512, smem_bytes>>>(d_kan, d_W2T, nullptr, outAB, outBias, outO);

    add_bias<<<(B * 64 + 255) / 256, 256>>>(outBias, outO, B * 64);
}